// round 2
// baseline (speedup 1.0000x reference)
#include <cuda_runtime.h>
#include <cuda_bf16.h>
#include <cstdint>

// ---------------------------------------------------------------------------
// SimCLR (NT-Xent) loss, B=4096, D=128, T=0.1
// loss = [ Sum_r log( Sum_{j!=r} exp(sim_rj/T) ) - (1/T) Sum_r pos_r ] / (2B)
// ---------------------------------------------------------------------------

#define BROWS    4096
#define TWOB     8192
#define DDIM     128
#define NTILES   64              // 8192 / 128 col tiles
#define SMEM_STRIDE 136          // 128 + 8 bf16 pad -> conflict-free b32 LDS
#define EXP_SCALE 14.4269504089f // 10 * log2(e) : exp(s/0.1) = exp2(s*this)

// scratch (no allocations allowed -> __device__ globals)
__device__ __nv_bfloat16 g_zb[TWOB * DDIM];     // normalized z, bf16 (2MB)
__device__ float         g_zf[TWOB * DDIM];     // normalized z, fp32 (4MB)
__device__ float         g_partial[NTILES * TWOB]; // per-(coltile,row) exp sums
__device__ float         g_pos[BROWS];          // fp32 positive dots
__device__ float         g_ploss[NTILES];       // per-block log sums

// ---------------------------------------------------------------------------
__device__ __forceinline__ float ex2f(float x) {
    float y;
    asm("ex2.approx.ftz.f32 %0, %1;" : "=f"(y) : "f"(x));
    return y;
}

__device__ __forceinline__ void mma16816(float& c0, float& c1, float& c2, float& c3,
                                         uint32_t a0, uint32_t a1, uint32_t a2, uint32_t a3,
                                         uint32_t b0, uint32_t b1) {
    asm volatile(
        "mma.sync.aligned.m16n8k16.row.col.f32.bf16.bf16.f32 "
        "{%0,%1,%2,%3}, {%4,%5,%6,%7}, {%8,%9}, {%0,%1,%2,%3};"
        : "+f"(c0), "+f"(c1), "+f"(c2), "+f"(c3)
        : "r"(a0), "r"(a1), "r"(a2), "r"(a3), "r"(b0), "r"(b1));
}

__device__ __forceinline__ uint32_t lds32(const __nv_bfloat16* p) {
    return *reinterpret_cast<const uint32_t*>(p);
}

// ---------------------------------------------------------------------------
// K1: L2-normalize rows of [x_i; x_j] -> g_zf (fp32) and g_zb (bf16)
// one block (128 thr) per row
__global__ void k_normalize(const float* __restrict__ xi, const float* __restrict__ xj) {
    int row = blockIdx.x;
    int t   = threadIdx.x;
    const float* src = (row < BROWS) ? (xi + row * DDIM) : (xj + (row - BROWS) * DDIM);
    float v  = src[t];
    float ss = v * v;
    #pragma unroll
    for (int o = 16; o > 0; o >>= 1) ss += __shfl_xor_sync(0xffffffffu, ss, o);
    __shared__ float sred[4];
    int lane = t & 31, wid = t >> 5;
    if (lane == 0) sred[wid] = ss;
    __syncthreads();
    float tot = sred[0] + sred[1] + sred[2] + sred[3];
    float inv = 1.0f / fmaxf(sqrtf(tot), 1e-12f);
    float z = v * inv;
    g_zf[row * DDIM + t] = z;
    g_zb[row * DDIM + t] = __float2bfloat16(z);
}

// ---------------------------------------------------------------------------
// K2: fused tile GEMM (z z^T) + masked exp + per-row partial sums.
// grid (64 coltiles, 64 rowtiles), 256 threads, 128x128x128 tile, bf16 HMMA.
// Warp w owns rows [w*16, w*16+16) of the tile across all 128 cols.
__global__ void k_gemm_exp(void) {
    extern __shared__ __nv_bfloat16 smem[];
    __nv_bfloat16* sA = smem;                          // [128][136]
    __nv_bfloat16* sB = smem + 128 * SMEM_STRIDE;      // [128][136]

    const int colTile = blockIdx.x;
    const int rowTile = blockIdx.y;
    const int tid  = threadIdx.x;
    const int lane = tid & 31;
    const int wid  = tid >> 5;
    const int g    = lane >> 2;   // 0..7
    const int q    = lane & 3;    // 0..3

    // load A and B tiles (128 rows x 128 bf16 each) via uint4
    {
        const __nv_bfloat16* gA = g_zb + rowTile * 128 * DDIM;
        const __nv_bfloat16* gB = g_zb + colTile * 128 * DDIM;
        #pragma unroll
        for (int i = tid; i < 2048; i += 256) {
            int r = i >> 4, c = i & 15;
            *reinterpret_cast<uint4*>(&sA[r * SMEM_STRIDE + c * 8]) =
                *reinterpret_cast<const uint4*>(&gA[r * DDIM + c * 8]);
            *reinterpret_cast<uint4*>(&sB[r * SMEM_STRIDE + c * 8]) =
                *reinterpret_cast<const uint4*>(&gB[r * DDIM + c * 8]);
        }
    }
    __syncthreads();

    float c[16][4];
    #pragma unroll
    for (int n = 0; n < 16; n++)
        #pragma unroll
        for (int e = 0; e < 4; e++) c[n][e] = 0.0f;

    const int row0 = wid * 16 + g;
    const int row1 = row0 + 8;

    #pragma unroll
    for (int ks = 0; ks < 8; ks++) {
        const int k0 = ks * 16 + 2 * q;
        uint32_t a0 = lds32(&sA[row0 * SMEM_STRIDE + k0]);
        uint32_t a1 = lds32(&sA[row1 * SMEM_STRIDE + k0]);
        uint32_t a2 = lds32(&sA[row0 * SMEM_STRIDE + k0 + 8]);
        uint32_t a3 = lds32(&sA[row1 * SMEM_STRIDE + k0 + 8]);
        #pragma unroll
        for (int n = 0; n < 16; n++) {
            const int nb = n * 8 + g;
            uint32_t b0 = lds32(&sB[nb * SMEM_STRIDE + k0]);
            uint32_t b1 = lds32(&sB[nb * SMEM_STRIDE + k0 + 8]);
            mma16816(c[n][0], c[n][1], c[n][2], c[n][3], a0, a1, a2, a3, b0, b1);
        }
    }

    // epilogue: exp2(s * EXP_SCALE), mask diagonal, per-row sums
    const int grow0 = rowTile * 128 + wid * 16 + g;
    const int grow1 = grow0 + 8;
    float rs0 = 0.0f, rs1 = 0.0f;
    #pragma unroll
    for (int n = 0; n < 16; n++) {
        const int gc = colTile * 128 + n * 8 + 2 * q;
        float v0 = ex2f(c[n][0] * EXP_SCALE); if (grow0 == gc)     v0 = 0.0f;
        float v1 = ex2f(c[n][1] * EXP_SCALE); if (grow0 == gc + 1) v1 = 0.0f;
        float v2 = ex2f(c[n][2] * EXP_SCALE); if (grow1 == gc)     v2 = 0.0f;
        float v3 = ex2f(c[n][3] * EXP_SCALE); if (grow1 == gc + 1) v3 = 0.0f;
        rs0 += v0 + v1;
        rs1 += v2 + v3;
    }
    // combine the 4 lanes (q=0..3) that share rows (grow0, grow1)
    rs0 += __shfl_xor_sync(0xffffffffu, rs0, 1);
    rs0 += __shfl_xor_sync(0xffffffffu, rs0, 2);
    rs1 += __shfl_xor_sync(0xffffffffu, rs1, 1);
    rs1 += __shfl_xor_sync(0xffffffffu, rs1, 2);
    if (q == 0) {
        g_partial[colTile * TWOB + grow0] = rs0;
        g_partial[colTile * TWOB + grow1] = rs1;
    }
}

// ---------------------------------------------------------------------------
// K2b: fp32 positives  pos[i] = z_i . z_{i+B}   (one warp per i)
__global__ void k_pos(void) {
    int w    = blockIdx.x * 8 + (threadIdx.x >> 5);
    int lane = threadIdx.x & 31;
    const float* pa = g_zf + w * DDIM;
    const float* pb = g_zf + (w + BROWS) * DDIM;
    float s = 0.0f;
    #pragma unroll
    for (int e = 0; e < 4; e++) s += pa[lane + 32 * e] * pb[lane + 32 * e];
    #pragma unroll
    for (int o = 16; o > 0; o >>= 1) s += __shfl_xor_sync(0xffffffffu, s, o);
    if (lane == 0) g_pos[w] = s;
}

// ---------------------------------------------------------------------------
// K3: per row, sum the 64 col-tile partials, take log; block-sum 128 logs
__global__ void k_logsum(void) {
    int row = blockIdx.x * 128 + threadIdx.x;
    float s = 0.0f;
    #pragma unroll
    for (int cc = 0; cc < NTILES; cc++) s += g_partial[cc * TWOB + row];
    float lg = logf(s);
    #pragma unroll
    for (int o = 16; o > 0; o >>= 1) lg += __shfl_xor_sync(0xffffffffu, lg, o);
    __shared__ float sred[4];
    int lane = threadIdx.x & 31, wid = threadIdx.x >> 5;
    if (lane == 0) sred[wid] = lg;
    __syncthreads();
    if (threadIdx.x == 0)
        g_ploss[blockIdx.x] = sred[0] + sred[1] + sred[2] + sred[3];
}

// ---------------------------------------------------------------------------
// K4: final scalar: (sum logs - 20 * sum pos) / 8192
__global__ void k_finalize(float* __restrict__ out) {
    int tid = threadIdx.x;
    float acc = 0.0f;
    for (int j = tid; j < BROWS; j += 256) acc += g_pos[j];
    acc *= -20.0f;                          // -(2/T) * sum_i pos_i contribution
    if (tid < NTILES) acc += g_ploss[tid];
    #pragma unroll
    for (int o = 16; o > 0; o >>= 1) acc += __shfl_xor_sync(0xffffffffu, acc, o);
    __shared__ float sred[8];
    int lane = tid & 31, wid = tid >> 5;
    if (lane == 0) sred[wid] = acc;
    __syncthreads();
    if (tid == 0) {
        float tot = 0.0f;
        #pragma unroll
        for (int w = 0; w < 8; w++) tot += sred[w];
        out[0] = tot / (float)TWOB;         // sum / (2B) = sum / 8192
    }
}

// ---------------------------------------------------------------------------
extern "C" void kernel_launch(void* const* d_in, const int* in_sizes, int n_in,
                              void* d_out, int out_size) {
    const float* xi = (const float*)d_in[0];
    const float* xj = (const float*)d_in[1];
    float* out = (float*)d_out;

    k_normalize<<<TWOB, 128>>>(xi, xj);

    const int smem_bytes = 2 * 128 * SMEM_STRIDE * (int)sizeof(__nv_bfloat16); // 69632
    cudaFuncSetAttribute(k_gemm_exp, cudaFuncAttributeMaxDynamicSharedMemorySize, smem_bytes);
    k_gemm_exp<<<dim3(NTILES, NTILES), 256, smem_bytes>>>();

    k_pos<<<BROWS / 8, 256>>>();
    k_logsum<<<NTILES, 128>>>();
    k_finalize<<<1, 256>>>(out);
}

// round 3
// speedup vs baseline: 1.3209x; 1.3209x over previous
#include <cuda_runtime.h>
#include <cuda_bf16.h>
#include <cstdint>

// ---------------------------------------------------------------------------
// SimCLR (NT-Xent) loss, B=4096, D=128, T=0.1
// Symmetric-GEMM formulation: only tiles rt<=ct computed; off-diag tiles emit
// row sums AND col sums (= mirrored row sums).
// ---------------------------------------------------------------------------

#define BROWS    4096
#define TWOB     8192
#define DDIM     128
#define NTILES   64
#define NBLOCKS  (NTILES * (NTILES + 1) / 2)   // 2080
#define SMEM_STRIDE 136
#define EXP_SCALE 14.4269504089f               // 10 * log2(e)

__device__ __nv_bfloat16 g_zb[TWOB * DDIM];
__device__ float         g_zf[TWOB * DDIM];
__device__ float         g_partial[TWOB * NTILES];  // [row][tile]
__device__ float         g_pos[BROWS];
__device__ float         g_ploss[32];

// ---------------------------------------------------------------------------
__device__ __forceinline__ float ex2f(float x) {
    float y;
    asm("ex2.approx.ftz.f32 %0, %1;" : "=f"(y) : "f"(x));
    return y;
}

__device__ __forceinline__ void mma16816(float& c0, float& c1, float& c2, float& c3,
                                         uint32_t a0, uint32_t a1, uint32_t a2, uint32_t a3,
                                         uint32_t b0, uint32_t b1) {
    asm volatile(
        "mma.sync.aligned.m16n8k16.row.col.f32.bf16.bf16.f32 "
        "{%0,%1,%2,%3}, {%4,%5,%6,%7}, {%8,%9}, {%0,%1,%2,%3};"
        : "+f"(c0), "+f"(c1), "+f"(c2), "+f"(c3)
        : "r"(a0), "r"(a1), "r"(a2), "r"(a3), "r"(b0), "r"(b1));
}

__device__ __forceinline__ uint32_t lds32(const __nv_bfloat16* p) {
    return *reinterpret_cast<const uint32_t*>(p);
}

// ---------------------------------------------------------------------------
// K1: normalize
__global__ void k_normalize(const float* __restrict__ xi, const float* __restrict__ xj) {
    int row = blockIdx.x;
    int t   = threadIdx.x;
    const float* src = (row < BROWS) ? (xi + row * DDIM) : (xj + (row - BROWS) * DDIM);
    float v  = src[t];
    float ss = v * v;
    #pragma unroll
    for (int o = 16; o > 0; o >>= 1) ss += __shfl_xor_sync(0xffffffffu, ss, o);
    __shared__ float sred[4];
    int lane = t & 31, wid = t >> 5;
    if (lane == 0) sred[wid] = ss;
    __syncthreads();
    float tot = sred[0] + sred[1] + sred[2] + sred[3];
    float inv = 1.0f / fmaxf(sqrtf(tot), 1e-12f);
    float z = v * inv;
    g_zf[row * DDIM + t] = z;
    g_zb[row * DDIM + t] = __float2bfloat16(z);
}

// ---------------------------------------------------------------------------
// K2: triangular fused GEMM + exp + row/col sums.
// 256 thr = 8 warps as 4(m) x 2(n). Warp tile 32x64, block tile 128x128.
__global__ __launch_bounds__(256, 2) void k_gemm_exp(void) {
    extern __shared__ __nv_bfloat16 smem[];
    __nv_bfloat16* sA = smem;
    __nv_bfloat16* sB = smem + 128 * SMEM_STRIDE;
    __shared__ float srow[2][128];   // per warp-col partial row sums
    __shared__ float scol[4][128];   // per warp-row partial col sums

    // decode triangular (rt <= ct)
    int rem = blockIdx.x, rt = 0;
    while (rem >= NTILES - rt) { rem -= NTILES - rt; rt++; }
    const int ct = rt + rem;
    const bool diag = (rt == ct);

    const int tid  = threadIdx.x;
    const int lane = tid & 31;
    const int wid  = tid >> 5;
    const int g    = lane >> 2;      // 0..7
    const int q    = lane & 3;       // 0..3
    const int wr   = wid & 3;        // warp m-row 0..3
    const int wc   = wid >> 2;       // warp n-col 0..1

    {
        const __nv_bfloat16* gA = g_zb + rt * 128 * DDIM;
        const __nv_bfloat16* gB = g_zb + ct * 128 * DDIM;
        #pragma unroll
        for (int i = tid; i < 2048; i += 256) {
            int r = i >> 4, c8 = i & 15;
            *reinterpret_cast<uint4*>(&sA[r * SMEM_STRIDE + c8 * 8]) =
                *reinterpret_cast<const uint4*>(&gA[r * DDIM + c8 * 8]);
            *reinterpret_cast<uint4*>(&sB[r * SMEM_STRIDE + c8 * 8]) =
                *reinterpret_cast<const uint4*>(&gB[r * DDIM + c8 * 8]);
        }
    }
    __syncthreads();

    float c[2][8][4];
    #pragma unroll
    for (int mi = 0; mi < 2; mi++)
        #pragma unroll
        for (int ni = 0; ni < 8; ni++)
            #pragma unroll
            for (int e = 0; e < 4; e++) c[mi][ni][e] = 0.0f;

    const int m0 = wr * 32 + g;
    const int n0 = wc * 64 + g;

    #pragma unroll
    for (int ks = 0; ks < 8; ks++) {
        const int k0 = ks * 16 + 2 * q;
        uint32_t a[2][4];
        #pragma unroll
        for (int mi = 0; mi < 2; mi++) {
            const int r0 = m0 + mi * 16;
            a[mi][0] = lds32(&sA[r0 * SMEM_STRIDE + k0]);
            a[mi][1] = lds32(&sA[(r0 + 8) * SMEM_STRIDE + k0]);
            a[mi][2] = lds32(&sA[r0 * SMEM_STRIDE + k0 + 8]);
            a[mi][3] = lds32(&sA[(r0 + 8) * SMEM_STRIDE + k0 + 8]);
        }
        #pragma unroll
        for (int ni = 0; ni < 8; ni++) {
            const int nb = n0 + ni * 8;
            uint32_t b0 = lds32(&sB[nb * SMEM_STRIDE + k0]);
            uint32_t b1 = lds32(&sB[nb * SMEM_STRIDE + k0 + 8]);
            #pragma unroll
            for (int mi = 0; mi < 2; mi++)
                mma16816(c[mi][ni][0], c[mi][ni][1], c[mi][ni][2], c[mi][ni][3],
                         a[mi][0], a[mi][1], a[mi][2], a[mi][3], b0, b1);
        }
    }

    // ---- epilogue: exp, diag mask, row+col sums ----
    float rs[2][2];
    rs[0][0] = rs[0][1] = rs[1][0] = rs[1][1] = 0.0f;

    #pragma unroll
    for (int ni = 0; ni < 8; ni++) {
        const int lc = wc * 64 + ni * 8 + 2 * q;  // local col of v0/v2; +1 for v1/v3
        float cs0 = 0.0f, cs1 = 0.0f;
        #pragma unroll
        for (int mi = 0; mi < 2; mi++) {
            const int lr0 = wr * 32 + mi * 16 + g;
            const int lr1 = lr0 + 8;
            float v0 = ex2f(c[mi][ni][0] * EXP_SCALE);
            float v1 = ex2f(c[mi][ni][1] * EXP_SCALE);
            float v2 = ex2f(c[mi][ni][2] * EXP_SCALE);
            float v3 = ex2f(c[mi][ni][3] * EXP_SCALE);
            if (diag) {
                if (lr0 == lc)     v0 = 0.0f;
                if (lr0 == lc + 1) v1 = 0.0f;
                if (lr1 == lc)     v2 = 0.0f;
                if (lr1 == lc + 1) v3 = 0.0f;
            }
            rs[mi][0] += v0 + v1;
            rs[mi][1] += v2 + v3;
            cs0 += v0 + v2;
            cs1 += v1 + v3;
        }
        if (!diag) {
            // reduce over g (lanes xor 4,8,16) -> valid at lanes 0..3 (g==0)
            cs0 += __shfl_xor_sync(0xffffffffu, cs0, 4);
            cs0 += __shfl_xor_sync(0xffffffffu, cs0, 8);
            cs0 += __shfl_xor_sync(0xffffffffu, cs0, 16);
            cs1 += __shfl_xor_sync(0xffffffffu, cs1, 4);
            cs1 += __shfl_xor_sync(0xffffffffu, cs1, 8);
            cs1 += __shfl_xor_sync(0xffffffffu, cs1, 16);
            if (lane < 4) {
                scol[wr][lc]     = cs0;
                scol[wr][lc + 1] = cs1;
            }
        }
    }

    // row sums: reduce over q (xor 1,2) -> valid at q==0 lanes
    #pragma unroll
    for (int mi = 0; mi < 2; mi++) {
        rs[mi][0] += __shfl_xor_sync(0xffffffffu, rs[mi][0], 1);
        rs[mi][0] += __shfl_xor_sync(0xffffffffu, rs[mi][0], 2);
        rs[mi][1] += __shfl_xor_sync(0xffffffffu, rs[mi][1], 1);
        rs[mi][1] += __shfl_xor_sync(0xffffffffu, rs[mi][1], 2);
    }
    if (q == 0) {
        #pragma unroll
        for (int mi = 0; mi < 2; mi++) {
            const int lr = wr * 32 + mi * 16 + g;
            srow[wc][lr]     = rs[mi][0];
            srow[wc][lr + 8] = rs[mi][1];
        }
    }
    __syncthreads();

    if (tid < 128) {
        float v = srow[0][tid] + srow[1][tid];
        g_partial[(rt * 128 + tid) * NTILES + ct] = v;
    } else if (!diag) {
        const int cI = tid - 128;
        float v = scol[0][cI] + scol[1][cI] + scol[2][cI] + scol[3][cI];
        g_partial[(ct * 128 + cI) * NTILES + rt] = v;
    }
}

// ---------------------------------------------------------------------------
// K2b: fp32 positives (one warp per pair)
__global__ void k_pos(void) {
    int w    = blockIdx.x * 8 + (threadIdx.x >> 5);
    int lane = threadIdx.x & 31;
    const float* pa = g_zf + w * DDIM;
    const float* pb = g_zf + (w + BROWS) * DDIM;
    float s = 0.0f;
    #pragma unroll
    for (int e = 0; e < 4; e++) s += pa[lane + 32 * e] * pb[lane + 32 * e];
    #pragma unroll
    for (int o = 16; o > 0; o >>= 1) s += __shfl_xor_sync(0xffffffffu, s, o);
    if (lane == 0) g_pos[w] = s;
}

// ---------------------------------------------------------------------------
// K3: per-row sum of 64 contiguous partials (float4 x16, high MLP), log, reduce
__global__ void k_logsum(void) {
    int row = blockIdx.x * 256 + threadIdx.x;
    const float4* p = reinterpret_cast<const float4*>(g_partial + row * NTILES);
    float s = 0.0f;
    #pragma unroll
    for (int i = 0; i < 16; i++) {
        float4 v = p[i];
        s += (v.x + v.y) + (v.z + v.w);
    }
    float lg = logf(s);
    #pragma unroll
    for (int o = 16; o > 0; o >>= 1) lg += __shfl_xor_sync(0xffffffffu, lg, o);
    __shared__ float sred[8];
    int lane = threadIdx.x & 31, wid = threadIdx.x >> 5;
    if (lane == 0) sred[wid] = lg;
    __syncthreads();
    if (threadIdx.x == 0) {
        float t = 0.0f;
        #pragma unroll
        for (int w = 0; w < 8; w++) t += sred[w];
        g_ploss[blockIdx.x] = t;
    }
}

// ---------------------------------------------------------------------------
// K4: final scalar: (sum logs - 20 * sum pos) / 8192
__global__ void k_finalize(float* __restrict__ out) {
    int tid = threadIdx.x;
    float acc = 0.0f;
    for (int j = tid; j < BROWS; j += 256) acc += g_pos[j];
    acc *= -20.0f;
    if (tid < 32) acc += g_ploss[tid];
    #pragma unroll
    for (int o = 16; o > 0; o >>= 1) acc += __shfl_xor_sync(0xffffffffu, acc, o);
    __shared__ float sred[8];
    int lane = tid & 31, wid = tid >> 5;
    if (lane == 0) sred[wid] = acc;
    __syncthreads();
    if (tid == 0) {
        float tot = 0.0f;
        #pragma unroll
        for (int w = 0; w < 8; w++) tot += sred[w];
        out[0] = tot / (float)TWOB;
    }
}

// ---------------------------------------------------------------------------
extern "C" void kernel_launch(void* const* d_in, const int* in_sizes, int n_in,
                              void* d_out, int out_size) {
    const float* xi = (const float*)d_in[0];
    const float* xj = (const float*)d_in[1];
    float* out = (float*)d_out;

    k_normalize<<<TWOB, 128>>>(xi, xj);

    const int smem_bytes = 2 * 128 * SMEM_STRIDE * (int)sizeof(__nv_bfloat16); // 69632
    cudaFuncSetAttribute(k_gemm_exp, cudaFuncAttributeMaxDynamicSharedMemorySize, smem_bytes);
    k_gemm_exp<<<NBLOCKS, 256, smem_bytes>>>();

    k_pos<<<BROWS / 8, 256>>>();
    k_logsum<<<TWOB / 256, 256>>>();
    k_finalize<<<1, 256>>>(out);
}

// round 4
// speedup vs baseline: 1.3603x; 1.0298x over previous
#include <cuda_runtime.h>
#include <cuda_bf16.h>
#include <cstdint>

// ---------------------------------------------------------------------------
// SimCLR (NT-Xent) loss, B=4096, D=128, T=0.1 — symmetric triangular GEMM
// ---------------------------------------------------------------------------

#define BROWS    4096
#define TWOB     8192
#define DDIM     128
#define NTILES   64
#define NBLOCKS  (NTILES * (NTILES + 1) / 2)   // 2080
#define SMEM_STRIDE 136
#define EXP_SCALE 14.4269504089f               // 10 * log2(e)

__device__ __nv_bfloat16 g_zb[TWOB * DDIM];
__device__ float         g_zf[TWOB * DDIM];
__device__ float         g_partial[TWOB * NTILES];  // [row][tile]
__device__ float         g_pos[BROWS];
__device__ float         g_ploss[32];

// ---------------------------------------------------------------------------
__device__ __forceinline__ float ex2f(float x) {
    float y;
    asm("ex2.approx.ftz.f32 %0, %1;" : "=f"(y) : "f"(x));
    return y;
}

__device__ __forceinline__ void mma16816(float& c0, float& c1, float& c2, float& c3,
                                         uint32_t a0, uint32_t a1, uint32_t a2, uint32_t a3,
                                         uint32_t b0, uint32_t b1) {
    asm volatile(
        "mma.sync.aligned.m16n8k16.row.col.f32.bf16.bf16.f32 "
        "{%0,%1,%2,%3}, {%4,%5,%6,%7}, {%8,%9}, {%0,%1,%2,%3};"
        : "+f"(c0), "+f"(c1), "+f"(c2), "+f"(c3)
        : "r"(a0), "r"(a1), "r"(a2), "r"(a3), "r"(b0), "r"(b1));
}

__device__ __forceinline__ void ldsm_x4(uint32_t& r0, uint32_t& r1, uint32_t& r2, uint32_t& r3,
                                        uint32_t saddr) {
    asm volatile("ldmatrix.sync.aligned.m8n8.x4.shared.b16 {%0,%1,%2,%3}, [%4];"
                 : "=r"(r0), "=r"(r1), "=r"(r2), "=r"(r3) : "r"(saddr));
}

// ---------------------------------------------------------------------------
// K1: normalize, warp-per-row
__global__ void k_normalize(const float* __restrict__ xi, const float* __restrict__ xj) {
    int row  = blockIdx.x * 8 + (threadIdx.x >> 5);
    int lane = threadIdx.x & 31;
    const float* src = (row < BROWS) ? (xi + row * DDIM) : (xj + (row - BROWS) * DDIM);
    float4 v = *reinterpret_cast<const float4*>(src + lane * 4);
    float ss = v.x * v.x + v.y * v.y + v.z * v.z + v.w * v.w;
    #pragma unroll
    for (int o = 16; o > 0; o >>= 1) ss += __shfl_xor_sync(0xffffffffu, ss, o);
    float inv = 1.0f / fmaxf(sqrtf(ss), 1e-12f);
    float4 z;
    z.x = v.x * inv; z.y = v.y * inv; z.z = v.z * inv; z.w = v.w * inv;
    *reinterpret_cast<float4*>(g_zf + row * DDIM + lane * 4) = z;
    __nv_bfloat162 b0 = __floats2bfloat162_rn(z.x, z.y);
    __nv_bfloat162 b1 = __floats2bfloat162_rn(z.z, z.w);
    uint32_t u0 = *reinterpret_cast<uint32_t*>(&b0);
    uint32_t u1 = *reinterpret_cast<uint32_t*>(&b1);
    uint2 pk = make_uint2(u0, u1);
    *reinterpret_cast<uint2*>(g_zb + row * DDIM + lane * 4) = pk;
}

// ---------------------------------------------------------------------------
// K2: triangular fused GEMM + exp + row/col sums. 8 warps = 4(m) x 2(n),
// warp tile 32x64. Fragments loaded via ldmatrix.x4.
__global__ __launch_bounds__(256, 2) void k_gemm_exp(void) {
    extern __shared__ __nv_bfloat16 smem[];
    __nv_bfloat16* sA = smem;
    __nv_bfloat16* sB = smem + 128 * SMEM_STRIDE;
    __shared__ float srow[2][128];
    __shared__ float scol[4][128];

    int rem = blockIdx.x, rt = 0;
    while (rem >= NTILES - rt) { rem -= NTILES - rt; rt++; }
    const int ct = rt + rem;
    const bool diag = (rt == ct);

    const int tid  = threadIdx.x;
    const int lane = tid & 31;
    const int wid  = tid >> 5;
    const int g    = lane >> 2;      // 0..7
    const int q    = lane & 3;       // 0..3
    const int wr   = wid & 3;        // warp m-row 0..3
    const int wc   = wid >> 2;       // warp n-col 0..1

    {
        const __nv_bfloat16* gA = g_zb + rt * 128 * DDIM;
        const __nv_bfloat16* gB = g_zb + ct * 128 * DDIM;
        #pragma unroll
        for (int i = tid; i < 2048; i += 256) {
            int r = i >> 4, c8 = i & 15;
            *reinterpret_cast<uint4*>(&sA[r * SMEM_STRIDE + c8 * 8]) =
                *reinterpret_cast<const uint4*>(&gA[r * DDIM + c8 * 8]);
            *reinterpret_cast<uint4*>(&sB[r * SMEM_STRIDE + c8 * 8]) =
                *reinterpret_cast<const uint4*>(&gB[r * DDIM + c8 * 8]);
        }
    }
    __syncthreads();

    // ldmatrix per-lane base addresses (byte offsets into shared space)
    const int sub = lane >> 3;       // 0..3 (which 8x8 matrix)
    const int li  = lane & 7;        // row within matrix
    // A (non-trans): sub0:(r+i,k0) sub1:(r+i+8,k0) sub2:(r+i,k8) sub3:(r+i+8,k8)
    const int aRow0 = wr * 32 + li + ((sub & 1) << 3);
    const int aKoff = (sub >> 1) << 3;
    uint32_t aAddr0 = (uint32_t)__cvta_generic_to_shared(&sA[aRow0 * SMEM_STRIDE + aKoff]);
    uint32_t aAddr1 = (uint32_t)__cvta_generic_to_shared(&sA[(aRow0 + 16) * SMEM_STRIDE + aKoff]);
    // B (non-trans): sub0:(n+i,k0) sub1:(n+i,k8) sub2:(n+8+i,k0) sub3:(n+8+i,k8)
    const int bRow = wc * 64 + li + ((sub >> 1) << 3);
    const int bKoff = (sub & 1) << 3;
    uint32_t bAddr = (uint32_t)__cvta_generic_to_shared(&sB[bRow * SMEM_STRIDE + bKoff]);

    float c[2][8][4];
    #pragma unroll
    for (int mi = 0; mi < 2; mi++)
        #pragma unroll
        for (int ni = 0; ni < 8; ni++)
            #pragma unroll
            for (int e = 0; e < 4; e++) c[mi][ni][e] = 0.0f;

    #pragma unroll
    for (int ks = 0; ks < 8; ks++) {
        const uint32_t kb = ks * 32;         // 16 bf16 = 32 bytes per k-step
        uint32_t a[2][4];
        ldsm_x4(a[0][0], a[0][1], a[0][2], a[0][3], aAddr0 + kb);
        ldsm_x4(a[1][0], a[1][1], a[1][2], a[1][3], aAddr1 + kb);
        #pragma unroll
        for (int p = 0; p < 4; p++) {
            uint32_t b00, b01, b10, b11;     // (b0,b1) for ni=2p and ni=2p+1
            ldsm_x4(b00, b01, b10, b11, bAddr + p * 16 * SMEM_STRIDE * 2 + kb);
            #pragma unroll
            for (int mi = 0; mi < 2; mi++) {
                mma16816(c[mi][2*p][0],   c[mi][2*p][1],   c[mi][2*p][2],   c[mi][2*p][3],
                         a[mi][0], a[mi][1], a[mi][2], a[mi][3], b00, b01);
                mma16816(c[mi][2*p+1][0], c[mi][2*p+1][1], c[mi][2*p+1][2], c[mi][2*p+1][3],
                         a[mi][0], a[mi][1], a[mi][2], a[mi][3], b10, b11);
            }
        }
    }

    // ---- epilogue: exp, diag mask, row+col sums ----
    float rs[2][2];
    rs[0][0] = rs[0][1] = rs[1][0] = rs[1][1] = 0.0f;

    #pragma unroll
    for (int ni = 0; ni < 8; ni++) {
        const int lc = wc * 64 + ni * 8 + 2 * q;
        float cs0 = 0.0f, cs1 = 0.0f;
        #pragma unroll
        for (int mi = 0; mi < 2; mi++) {
            const int lr0 = wr * 32 + mi * 16 + g;
            const int lr1 = lr0 + 8;
            float v0 = ex2f(c[mi][ni][0] * EXP_SCALE);
            float v1 = ex2f(c[mi][ni][1] * EXP_SCALE);
            float v2 = ex2f(c[mi][ni][2] * EXP_SCALE);
            float v3 = ex2f(c[mi][ni][3] * EXP_SCALE);
            if (diag) {
                if (lr0 == lc)     v0 = 0.0f;
                if (lr0 == lc + 1) v1 = 0.0f;
                if (lr1 == lc)     v2 = 0.0f;
                if (lr1 == lc + 1) v3 = 0.0f;
            }
            rs[mi][0] += v0 + v1;
            rs[mi][1] += v2 + v3;
            cs0 += v0 + v2;
            cs1 += v1 + v3;
        }
        if (!diag) {
            cs0 += __shfl_xor_sync(0xffffffffu, cs0, 4);
            cs0 += __shfl_xor_sync(0xffffffffu, cs0, 8);
            cs0 += __shfl_xor_sync(0xffffffffu, cs0, 16);
            cs1 += __shfl_xor_sync(0xffffffffu, cs1, 4);
            cs1 += __shfl_xor_sync(0xffffffffu, cs1, 8);
            cs1 += __shfl_xor_sync(0xffffffffu, cs1, 16);
            if (lane < 4) {
                scol[wr][lc]     = cs0;
                scol[wr][lc + 1] = cs1;
            }
        }
    }

    #pragma unroll
    for (int mi = 0; mi < 2; mi++) {
        rs[mi][0] += __shfl_xor_sync(0xffffffffu, rs[mi][0], 1);
        rs[mi][0] += __shfl_xor_sync(0xffffffffu, rs[mi][0], 2);
        rs[mi][1] += __shfl_xor_sync(0xffffffffu, rs[mi][1], 1);
        rs[mi][1] += __shfl_xor_sync(0xffffffffu, rs[mi][1], 2);
    }
    if (q == 0) {
        #pragma unroll
        for (int mi = 0; mi < 2; mi++) {
            const int lr = wr * 32 + mi * 16 + g;
            srow[wc][lr]     = rs[mi][0];
            srow[wc][lr + 8] = rs[mi][1];
        }
    }
    __syncthreads();

    if (tid < 128) {
        float v = srow[0][tid] + srow[1][tid];
        g_partial[(rt * 128 + tid) * NTILES + ct] = v;
    } else if (!diag) {
        const int cI = tid - 128;
        float v = scol[0][cI] + scol[1][cI] + scol[2][cI] + scol[3][cI];
        g_partial[(ct * 128 + cI) * NTILES + rt] = v;
    }
}

// ---------------------------------------------------------------------------
// K3 (fused): per-row log-sum of partials  +  fp32 positives
// grid 32 x 256 threads.
__global__ void k_reduce(void) {
    int tid = threadIdx.x;
    // part 1: log of row sums
    int row = blockIdx.x * 256 + tid;
    const float4* p = reinterpret_cast<const float4*>(g_partial + row * NTILES);
    float s = 0.0f;
    #pragma unroll
    for (int i = 0; i < 16; i++) {
        float4 v = p[i];
        s += (v.x + v.y) + (v.z + v.w);
    }
    float lg = logf(s);
    #pragma unroll
    for (int o = 16; o > 0; o >>= 1) lg += __shfl_xor_sync(0xffffffffu, lg, o);
    __shared__ float sred[8];
    int lane = tid & 31, wid = tid >> 5;
    if (lane == 0) sred[wid] = lg;
    __syncthreads();
    if (tid == 0) {
        float t = 0.0f;
        #pragma unroll
        for (int w = 0; w < 8; w++) t += sred[w];
        g_ploss[blockIdx.x] = t;
    }
    // part 2: positives — 128 pairs per block, 2 threads per pair
    int pr = blockIdx.x * 128 + (tid >> 1);
    int h  = tid & 1;
    const float4* pa = reinterpret_cast<const float4*>(g_zf + pr * DDIM + h * 64);
    const float4* pb = reinterpret_cast<const float4*>(g_zf + (pr + BROWS) * DDIM + h * 64);
    float d = 0.0f;
    #pragma unroll
    for (int e = 0; e < 16; e++) {
        float4 va = pa[e], vb = pb[e];
        d += va.x * vb.x + va.y * vb.y + va.z * vb.z + va.w * vb.w;
    }
    d += __shfl_xor_sync(0xffffffffu, d, 1);
    if (h == 0) g_pos[pr] = d;
}

// ---------------------------------------------------------------------------
// K4: final scalar: (sum logs - 20 * sum pos) / 8192
__global__ void k_finalize(float* __restrict__ out) {
    int tid = threadIdx.x;
    float acc = 0.0f;
    for (int j = tid; j < BROWS; j += 256) acc += g_pos[j];
    acc *= -20.0f;
    if (tid < 32) acc += g_ploss[tid];
    #pragma unroll
    for (int o = 16; o > 0; o >>= 1) acc += __shfl_xor_sync(0xffffffffu, acc, o);
    __shared__ float sred[8];
    int lane = tid & 31, wid = tid >> 5;
    if (lane == 0) sred[wid] = acc;
    __syncthreads();
    if (tid == 0) {
        float tot = 0.0f;
        #pragma unroll
        for (int w = 0; w < 8; w++) tot += sred[w];
        out[0] = tot / (float)TWOB;
    }
}

// ---------------------------------------------------------------------------
extern "C" void kernel_launch(void* const* d_in, const int* in_sizes, int n_in,
                              void* d_out, int out_size) {
    const float* xi = (const float*)d_in[0];
    const float* xj = (const float*)d_in[1];
    float* out = (float*)d_out;

    k_normalize<<<TWOB / 8, 256>>>(xi, xj);

    const int smem_bytes = 2 * 128 * SMEM_STRIDE * (int)sizeof(__nv_bfloat16); // 69632
    cudaFuncSetAttribute(k_gemm_exp, cudaFuncAttributeMaxDynamicSharedMemorySize, smem_bytes);
    k_gemm_exp<<<NBLOCKS, 256, smem_bytes>>>();

    k_reduce<<<32, 256>>>();
    k_finalize<<<1, 256>>>(out);
}

// round 6
// speedup vs baseline: 1.5151x; 1.1138x over previous
#include <cuda_runtime.h>
#include <cuda_bf16.h>
#include <cstdint>

// ---------------------------------------------------------------------------
// SimCLR (NT-Xent) loss, B=4096, D=128, T=0.1 — symmetric triangular GEMM
// mma.sync bf16 path (tcgen05 PTX rejected by harness toolchain: target sm_103)
// ---------------------------------------------------------------------------

#define BROWS    4096
#define TWOB     8192
#define DDIM     128
#define NTILES   64
#define NBLOCKS  (NTILES * (NTILES + 1) / 2)   // 2080
#define SMEM_STRIDE 136
#define EXP_SCALE 14.4269504089f               // 10 * log2(e)

__device__ __nv_bfloat16 g_zb[TWOB * DDIM];
__device__ float         g_zf[TWOB * DDIM];
__device__ float         g_partial[TWOB * NTILES];  // [row][tile]
__device__ float         g_ploss[32];
__device__ float         g_possum[32];

// ---------------------------------------------------------------------------
__device__ __forceinline__ float ex2f(float x) {
    float y;
    asm("ex2.approx.ftz.f32 %0, %1;" : "=f"(y) : "f"(x));
    return y;
}

__device__ __forceinline__ void mma16816(float& c0, float& c1, float& c2, float& c3,
                                         uint32_t a0, uint32_t a1, uint32_t a2, uint32_t a3,
                                         uint32_t b0, uint32_t b1) {
    asm volatile(
        "mma.sync.aligned.m16n8k16.row.col.f32.bf16.bf16.f32 "
        "{%0,%1,%2,%3}, {%4,%5,%6,%7}, {%8,%9}, {%0,%1,%2,%3};"
        : "+f"(c0), "+f"(c1), "+f"(c2), "+f"(c3)
        : "r"(a0), "r"(a1), "r"(a2), "r"(a3), "r"(b0), "r"(b1));
}

__device__ __forceinline__ void ldsm_x4(uint32_t& r0, uint32_t& r1, uint32_t& r2, uint32_t& r3,
                                        uint32_t saddr) {
    asm volatile("ldmatrix.sync.aligned.m8n8.x4.shared.b16 {%0,%1,%2,%3}, [%4];"
                 : "=r"(r0), "=r"(r1), "=r"(r2), "=r"(r3) : "r"(saddr));
}

// ---------------------------------------------------------------------------
// K1: normalize, warp-per-row
__global__ void k_normalize(const float* __restrict__ xi, const float* __restrict__ xj) {
    int row  = blockIdx.x * 8 + (threadIdx.x >> 5);
    int lane = threadIdx.x & 31;
    const float* src = (row < BROWS) ? (xi + row * DDIM) : (xj + (row - BROWS) * DDIM);
    float4 v = *reinterpret_cast<const float4*>(src + lane * 4);
    float ss = v.x * v.x + v.y * v.y + v.z * v.z + v.w * v.w;
    #pragma unroll
    for (int o = 16; o > 0; o >>= 1) ss += __shfl_xor_sync(0xffffffffu, ss, o);
    float inv = 1.0f / fmaxf(sqrtf(ss), 1e-12f);
    float4 z;
    z.x = v.x * inv; z.y = v.y * inv; z.z = v.z * inv; z.w = v.w * inv;
    *reinterpret_cast<float4*>(g_zf + row * DDIM + lane * 4) = z;
    __nv_bfloat162 b0 = __floats2bfloat162_rn(z.x, z.y);
    __nv_bfloat162 b1 = __floats2bfloat162_rn(z.z, z.w);
    uint2 pk = make_uint2(*reinterpret_cast<uint32_t*>(&b0),
                          *reinterpret_cast<uint32_t*>(&b1));
    *reinterpret_cast<uint2*>(g_zb + row * DDIM + lane * 4) = pk;
}

// no-op spacer so ncu's capture slot (4th launch) lands on k_gemm_exp
__global__ void k_nop(void) {}

// ---------------------------------------------------------------------------
// K2: triangular fused GEMM + exp + row/col sums. 8 warps = 4(m) x 2(n),
// warp tile 32x64, ldmatrix fragments.
__global__ __launch_bounds__(256, 2) void k_gemm_exp(void) {
    extern __shared__ __nv_bfloat16 smem[];
    __nv_bfloat16* sA = smem;
    __nv_bfloat16* sB = smem + 128 * SMEM_STRIDE;
    __shared__ float srow[2][128];
    __shared__ float scol[4][128];

    int rem = blockIdx.x, rt = 0;
    while (rem >= NTILES - rt) { rem -= NTILES - rt; rt++; }
    const int ct = rt + rem;
    const bool diag = (rt == ct);

    const int tid  = threadIdx.x;
    const int lane = tid & 31;
    const int wid  = tid >> 5;
    const int g    = lane >> 2;      // 0..7
    const int q    = lane & 3;       // 0..3
    const int wr   = wid & 3;        // warp m-row 0..3
    const int wc   = wid >> 2;       // warp n-col 0..1

    {
        const __nv_bfloat16* gA = g_zb + rt * 128 * DDIM;
        const __nv_bfloat16* gB = g_zb + ct * 128 * DDIM;
        #pragma unroll
        for (int i = tid; i < 2048; i += 256) {
            int r = i >> 4, c8 = i & 15;
            *reinterpret_cast<uint4*>(&sA[r * SMEM_STRIDE + c8 * 8]) =
                *reinterpret_cast<const uint4*>(&gA[r * DDIM + c8 * 8]);
            *reinterpret_cast<uint4*>(&sB[r * SMEM_STRIDE + c8 * 8]) =
                *reinterpret_cast<const uint4*>(&gB[r * DDIM + c8 * 8]);
        }
    }
    __syncthreads();

    // ldmatrix per-lane base addresses
    const int sub = lane >> 3;       // 0..3
    const int li  = lane & 7;
    const int aRow0 = wr * 32 + li + ((sub & 1) << 3);
    const int aKoff = (sub >> 1) << 3;
    uint32_t aAddr0 = (uint32_t)__cvta_generic_to_shared(&sA[aRow0 * SMEM_STRIDE + aKoff]);
    uint32_t aAddr1 = (uint32_t)__cvta_generic_to_shared(&sA[(aRow0 + 16) * SMEM_STRIDE + aKoff]);
    const int bRow = wc * 64 + li + ((sub >> 1) << 3);
    const int bKoff = (sub & 1) << 3;
    uint32_t bAddr = (uint32_t)__cvta_generic_to_shared(&sB[bRow * SMEM_STRIDE + bKoff]);

    float c[2][8][4];
    #pragma unroll
    for (int mi = 0; mi < 2; mi++)
        #pragma unroll
        for (int ni = 0; ni < 8; ni++)
            #pragma unroll
            for (int e = 0; e < 4; e++) c[mi][ni][e] = 0.0f;

    #pragma unroll
    for (int ks = 0; ks < 8; ks++) {
        const uint32_t kb = ks * 32;
        uint32_t a[2][4];
        ldsm_x4(a[0][0], a[0][1], a[0][2], a[0][3], aAddr0 + kb);
        ldsm_x4(a[1][0], a[1][1], a[1][2], a[1][3], aAddr1 + kb);
        #pragma unroll
        for (int p = 0; p < 4; p++) {
            uint32_t b00, b01, b10, b11;
            ldsm_x4(b00, b01, b10, b11, bAddr + p * 16 * SMEM_STRIDE * 2 + kb);
            #pragma unroll
            for (int mi = 0; mi < 2; mi++) {
                mma16816(c[mi][2*p][0],   c[mi][2*p][1],   c[mi][2*p][2],   c[mi][2*p][3],
                         a[mi][0], a[mi][1], a[mi][2], a[mi][3], b00, b01);
                mma16816(c[mi][2*p+1][0], c[mi][2*p+1][1], c[mi][2*p+1][2], c[mi][2*p+1][3],
                         a[mi][0], a[mi][1], a[mi][2], a[mi][3], b10, b11);
            }
        }
    }

    // ---- epilogue: exp, diag mask, row sums + deferred col-sum butterfly ----
    float rs[2][2];
    rs[0][0] = rs[0][1] = rs[1][0] = rs[1][1] = 0.0f;
    float cs[16];
    #pragma unroll
    for (int v = 0; v < 16; v++) cs[v] = 0.0f;

    #pragma unroll
    for (int ni = 0; ni < 8; ni++) {
        const int lc = wc * 64 + ni * 8 + 2 * q;
        #pragma unroll
        for (int mi = 0; mi < 2; mi++) {
            const int lr0 = wr * 32 + mi * 16 + g;
            const int lr1 = lr0 + 8;
            float v0 = ex2f(c[mi][ni][0] * EXP_SCALE);
            float v1 = ex2f(c[mi][ni][1] * EXP_SCALE);
            float v2 = ex2f(c[mi][ni][2] * EXP_SCALE);
            float v3 = ex2f(c[mi][ni][3] * EXP_SCALE);
            if (diag) {
                if (lr0 == lc)     v0 = 0.0f;
                if (lr0 == lc + 1) v1 = 0.0f;
                if (lr1 == lc)     v2 = 0.0f;
                if (lr1 == lc + 1) v3 = 0.0f;
            }
            rs[mi][0] += v0 + v1;
            rs[mi][1] += v2 + v3;
            cs[2 * ni]     += v0 + v2;
            cs[2 * ni + 1] += v1 + v3;
        }
    }

    if (!diag) {
        // transpose-reduce cs[16] over the 8 g-lanes (masks 4, 8, 16):
        // each lane ends with 2 column sums.
        #pragma unroll
        for (int i = 0; i < 8; i++) {
            float keep = (lane & 4) ? cs[i + 8] : cs[i];
            float give = (lane & 4) ? cs[i] : cs[i + 8];
            cs[i] = keep + __shfl_xor_sync(0xffffffffu, give, 4);
        }
        #pragma unroll
        for (int i = 0; i < 4; i++) {
            float keep = (lane & 8) ? cs[i + 4] : cs[i];
            float give = (lane & 8) ? cs[i] : cs[i + 4];
            cs[i] = keep + __shfl_xor_sync(0xffffffffu, give, 8);
        }
        #pragma unroll
        for (int i = 0; i < 2; i++) {
            float keep = (lane & 16) ? cs[i + 2] : cs[i];
            float give = (lane & 16) ? cs[i] : cs[i + 2];
            cs[i] = keep + __shfl_xor_sync(0xffffffffu, give, 16);
        }
        const int v0 = ((lane & 4) ? 8 : 0) + ((lane & 8) ? 4 : 0) + ((lane & 16) ? 2 : 0);
        const int col0 = wc * 64 + (v0 >> 1) * 8 + 2 * q;   // v0 even
        scol[wr][col0]     = cs[0];
        scol[wr][col0 + 1] = cs[1];
    }

    #pragma unroll
    for (int mi = 0; mi < 2; mi++) {
        rs[mi][0] += __shfl_xor_sync(0xffffffffu, rs[mi][0], 1);
        rs[mi][0] += __shfl_xor_sync(0xffffffffu, rs[mi][0], 2);
        rs[mi][1] += __shfl_xor_sync(0xffffffffu, rs[mi][1], 1);
        rs[mi][1] += __shfl_xor_sync(0xffffffffu, rs[mi][1], 2);
    }
    if (q == 0) {
        #pragma unroll
        for (int mi = 0; mi < 2; mi++) {
            const int lr = wr * 32 + mi * 16 + g;
            srow[wc][lr]     = rs[mi][0];
            srow[wc][lr + 8] = rs[mi][1];
        }
    }
    __syncthreads();

    if (tid < 128) {
        float v = srow[0][tid] + srow[1][tid];
        g_partial[(rt * 128 + tid) * NTILES + ct] = v;
    } else if (!diag) {
        const int cI = tid - 128;
        float v = scol[0][cI] + scol[1][cI] + scol[2][cI] + scol[3][cI];
        g_partial[(ct * 128 + cI) * NTILES + rt] = v;
    }
}

// ---------------------------------------------------------------------------
// K3: per-row log-sum + per-block positive sums. grid 32 x 256.
__global__ void k_reduce(void) {
    int tid = threadIdx.x;
    int lane = tid & 31, wid = tid >> 5;
    __shared__ float sred1[8], sred2[8];

    // part 1: log of row sums
    int row = blockIdx.x * 256 + tid;
    const float4* p = reinterpret_cast<const float4*>(g_partial + row * NTILES);
    float s = 0.0f;
    #pragma unroll
    for (int i = 0; i < 16; i++) {
        float4 v = p[i];
        s += (v.x + v.y) + (v.z + v.w);
    }
    float lg = logf(s);
    #pragma unroll
    for (int o = 16; o > 0; o >>= 1) lg += __shfl_xor_sync(0xffffffffu, lg, o);
    if (lane == 0) sred1[wid] = lg;

    // part 2: positives — 128 pairs per block, 2 threads per pair
    int pr = blockIdx.x * 128 + (tid >> 1);
    int h  = tid & 1;
    const float4* pa = reinterpret_cast<const float4*>(g_zf + pr * DDIM + h * 64);
    const float4* pb = reinterpret_cast<const float4*>(g_zf + (pr + BROWS) * DDIM + h * 64);
    float d = 0.0f;
    #pragma unroll
    for (int e = 0; e < 16; e++) {
        float4 va = pa[e], vb = pb[e];
        d += va.x * vb.x + va.y * vb.y + va.z * vb.z + va.w * vb.w;
    }
    d += __shfl_xor_sync(0xffffffffu, d, 1);
    float ps = (h == 0) ? d : 0.0f;
    #pragma unroll
    for (int o = 16; o > 0; o >>= 1) ps += __shfl_xor_sync(0xffffffffu, ps, o);
    if (lane == 0) sred2[wid] = ps;

    __syncthreads();
    if (tid == 0) {
        float t1 = 0.0f, t2 = 0.0f;
        #pragma unroll
        for (int i = 0; i < 8; i++) { t1 += sred1[i]; t2 += sred2[i]; }
        g_ploss[blockIdx.x]  = t1;
        g_possum[blockIdx.x] = t2;
    }
}

// ---------------------------------------------------------------------------
// K4: final scalar, single warp: (sum logs - 20 * sum pos) / 8192
__global__ void k_finalize(float* __restrict__ out) {
    int lane = threadIdx.x;
    float acc = g_ploss[lane] - 20.0f * g_possum[lane];
    #pragma unroll
    for (int o = 16; o > 0; o >>= 1) acc += __shfl_xor_sync(0xffffffffu, acc, o);
    if (lane == 0) out[0] = acc / (float)TWOB;
}

// ---------------------------------------------------------------------------
extern "C" void kernel_launch(void* const* d_in, const int* in_sizes, int n_in,
                              void* d_out, int out_size) {
    const float* xi = (const float*)d_in[0];
    const float* xj = (const float*)d_in[1];
    float* out = (float*)d_out;

    k_normalize<<<TWOB / 8, 256>>>(xi, xj);
    k_nop<<<1, 32>>>();
    k_nop<<<1, 32>>>();

    const int smem_bytes = 2 * 128 * SMEM_STRIDE * (int)sizeof(__nv_bfloat16); // 69632
    cudaFuncSetAttribute(k_gemm_exp, cudaFuncAttributeMaxDynamicSharedMemorySize, smem_bytes);
    k_gemm_exp<<<NBLOCKS, 256, smem_bytes>>>();

    k_reduce<<<32, 256>>>();
    k_finalize<<<1, 32>>>(out);
}

// round 7
// speedup vs baseline: 1.7177x; 1.1337x over previous
#include <cuda_runtime.h>
#include <cuda_bf16.h>
#include <cstdint>

// ---------------------------------------------------------------------------
// SimCLR (NT-Xent) loss, B=4096, D=128, T=0.1 — symmetric triangular GEMM.
// g_zb stored in tile-local SW128 two-slab layout so each GEMM block loads its
// 32KB tile with ONE cp.async.bulk (no LDG/STS wavefronts), LDSM conflict-free.
// ---------------------------------------------------------------------------

#define BROWS    4096
#define TWOB     8192
#define DDIM     128
#define NTILES   64
#define NBLOCKS  (NTILES * (NTILES + 1) / 2)   // 2080
#define TILE_BYTES 32768                       // 128 rows x 256B (two 16KB slabs)
#define SLAB_BYTES 16384
#define EXP_SCALE 14.4269504089f               // 10 * log2(e)

__device__ __nv_bfloat16 g_zb[TWOB * DDIM];    // swizzled tile layout (bytes)
__device__ float         g_zf[TWOB * DDIM];    // row-major fp32 (positives)
__device__ float         g_partial[TWOB * NTILES];  // [row][tile]
__device__ float         g_ploss[32];
__device__ float         g_possum[32];

// ---------------------------------------------------------------------------
__device__ __forceinline__ float ex2f(float x) {
    float y;
    asm("ex2.approx.ftz.f32 %0, %1;" : "=f"(y) : "f"(x));
    return y;
}

__device__ __forceinline__ void mma16816(float& c0, float& c1, float& c2, float& c3,
                                         uint32_t a0, uint32_t a1, uint32_t a2, uint32_t a3,
                                         uint32_t b0, uint32_t b1) {
    asm volatile(
        "mma.sync.aligned.m16n8k16.row.col.f32.bf16.bf16.f32 "
        "{%0,%1,%2,%3}, {%4,%5,%6,%7}, {%8,%9}, {%0,%1,%2,%3};"
        : "+f"(c0), "+f"(c1), "+f"(c2), "+f"(c3)
        : "r"(a0), "r"(a1), "r"(a2), "r"(a3), "r"(b0), "r"(b1));
}

__device__ __forceinline__ void ldsm_x4(uint32_t& r0, uint32_t& r1, uint32_t& r2, uint32_t& r3,
                                        uint32_t saddr) {
    asm volatile("ldmatrix.sync.aligned.m8n8.x4.shared.b16 {%0,%1,%2,%3}, [%4];"
                 : "=r"(r0), "=r"(r1), "=r"(r2), "=r"(r3) : "r"(saddr));
}

#define MBAR_WAIT_P0(m) do {                                                   \
    uint32_t _done;                                                            \
    asm volatile("{\n\t.reg .pred p;\n\t"                                      \
        "mbarrier.try_wait.parity.acquire.cta.shared::cta.b64 p, [%1], %2;\n\t"\
        "selp.b32 %0, 1, 0, p;\n\t}"                                           \
        : "=r"(_done) : "r"(m), "r"(0u) : "memory");                           \
    if (!_done) {                                                              \
        asm volatile("{\n\t.reg .pred P1;\n\t"                                 \
        "WL_%=:\n\t"                                                           \
        "mbarrier.try_wait.parity.acquire.cta.shared::cta.b64 P1, [%0], %1, 0x989680;\n\t" \
        "@P1 bra.uni WD_%=;\n\t"                                               \
        "bra.uni WL_%=;\n\t"                                                   \
        "WD_%=:\n\t}" :: "r"(m), "r"(0u) : "memory");                          \
    }                                                                          \
} while (0)

// ---------------------------------------------------------------------------
// K1: normalize, warp-per-row; write g_zb in tile-local SW128 2-slab layout.
__global__ void k_normalize(const float* __restrict__ xi, const float* __restrict__ xj) {
    int row  = blockIdx.x * 8 + (threadIdx.x >> 5);
    int lane = threadIdx.x & 31;
    const float* src = (row < BROWS) ? (xi + row * DDIM) : (xj + (row - BROWS) * DDIM);
    float4 v = *reinterpret_cast<const float4*>(src + lane * 4);
    float ss = v.x * v.x + v.y * v.y + v.z * v.z + v.w * v.w;
    #pragma unroll
    for (int o = 16; o > 0; o >>= 1) ss += __shfl_xor_sync(0xffffffffu, ss, o);
    float inv = 1.0f / fmaxf(sqrtf(ss), 1e-12f);
    float4 z;
    z.x = v.x * inv; z.y = v.y * inv; z.z = v.z * inv; z.w = v.w * inv;
    *reinterpret_cast<float4*>(g_zf + row * DDIM + lane * 4) = z;

    __nv_bfloat162 b0 = __floats2bfloat162_rn(z.x, z.y);
    __nv_bfloat162 b1 = __floats2bfloat162_rn(z.z, z.w);
    uint2 pk = make_uint2(*reinterpret_cast<uint32_t*>(&b0),
                          *reinterpret_cast<uint32_t*>(&b1));
    // tile-local swizzled address: tile = row>>7, slab = lane>>4 (k 0..63 / 64..127)
    char* dst = reinterpret_cast<char*>(g_zb)
              + (row >> 7) * TILE_BYTES + (lane >> 4) * SLAB_BYTES;
    uint32_t wb = (uint32_t)((row & 127) * 128 + (lane & 15) * 8);
    wb ^= (wb >> 3) & 0x70;                       // SW128 swizzle
    *reinterpret_cast<uint2*>(dst + wb) = pk;
}

// no-op spacer so ncu's capture slot (4th launch) lands on k_gemm_exp
__global__ void k_nop(void) {}

// ---------------------------------------------------------------------------
// K2: triangular fused GEMM + exp + row/col sums. 8 warps = 4(m) x 2(n),
// warp tile 32x64. Tiles fetched by cp.async.bulk; fragments via ldmatrix.
__global__ __launch_bounds__(256, 2) void k_gemm_exp(void) {
    extern __shared__ char dsm[];
    __shared__ __align__(8) uint64_t s_mbar;
    __shared__ float srow[2][128];
    __shared__ float scol[4][128];

    int rem = blockIdx.x, rt = 0;
    while (rem >= NTILES - rt) { rem -= NTILES - rt; rt++; }
    const int ct = rt + rem;
    const bool diag = (rt == ct);

    const int tid  = threadIdx.x;
    const int lane = tid & 31;
    const int wid  = tid >> 5;
    const int g    = lane >> 2;
    const int q    = lane & 3;
    const int wr   = wid & 3;        // warp m-row 0..3
    const int wc   = wid >> 2;       // warp n-col 0..1

    uint32_t dbase = (uint32_t)__cvta_generic_to_shared(dsm);
    uint32_t abase = (dbase + 1023u) & ~1023u;
    uint32_t bbase = diag ? abase : (abase + TILE_BYTES);
    const uint32_t mbar = (uint32_t)__cvta_generic_to_shared(&s_mbar);

    if (tid == 0)
        asm volatile("mbarrier.init.shared.b64 [%0], %1;" :: "r"(mbar), "r"(1u) : "memory");
    __syncthreads();
    if (tid == 0) {
        uint32_t total = diag ? TILE_BYTES : 2 * TILE_BYTES;
        asm volatile("mbarrier.arrive.expect_tx.shared.b64 _, [%0], %1;"
                     :: "r"(mbar), "r"(total) : "memory");
        const char* srcA = reinterpret_cast<const char*>(g_zb) + (size_t)rt * TILE_BYTES;
        asm volatile("cp.async.bulk.shared::cta.global.mbarrier::complete_tx::bytes "
                     "[%0], [%1], %2, [%3];"
                     :: "r"(abase), "l"(srcA), "r"((uint32_t)TILE_BYTES), "r"(mbar) : "memory");
        if (!diag) {
            const char* srcB = reinterpret_cast<const char*>(g_zb) + (size_t)ct * TILE_BYTES;
            asm volatile("cp.async.bulk.shared::cta.global.mbarrier::complete_tx::bytes "
                         "[%0], [%1], %2, [%3];"
                         :: "r"(bbase), "l"(srcB), "r"((uint32_t)TILE_BYTES), "r"(mbar) : "memory");
        }
    }

    // ldmatrix lane geometry (same fragment maps as the validated R4/R6 kernel)
    const int sub = lane >> 3;       // 0..3
    const int li  = lane & 7;
    const int aRow0 = wr * 32 + li + ((sub & 1) << 3);
    const int aK16  = (sub >> 1) << 4;            // 0 or 16 bytes
    const int xA    = (aRow0 & 7) << 4;           // swizzle XOR for this lane's rows
    const int bRow0 = wc * 64 + li + ((sub >> 1) << 3);
    const int bK16  = (sub & 1) << 4;
    const int xB    = (bRow0 & 7) << 4;

    MBAR_WAIT_P0(mbar);

    float c[2][8][4];
    #pragma unroll
    for (int mi = 0; mi < 2; mi++)
        #pragma unroll
        for (int ni = 0; ni < 8; ni++)
            #pragma unroll
            for (int e = 0; e < 4; e++) c[mi][ni][e] = 0.0f;

    #pragma unroll
    for (int ks = 0; ks < 8; ks++) {
        const uint32_t slab = (uint32_t)(ks >> 2) * SLAB_BYTES;
        const uint32_t kbA  = (uint32_t)(((ks & 3) * 32 + aK16) ^ xA);
        const uint32_t kbB  = (uint32_t)(((ks & 3) * 32 + bK16) ^ xB);
        uint32_t a[2][4];
        ldsm_x4(a[0][0], a[0][1], a[0][2], a[0][3],
                abase + slab + (uint32_t)aRow0 * 128 + kbA);
        ldsm_x4(a[1][0], a[1][1], a[1][2], a[1][3],
                abase + slab + (uint32_t)(aRow0 + 16) * 128 + kbA);
        #pragma unroll
        for (int p = 0; p < 4; p++) {
            uint32_t b00, b01, b10, b11;
            ldsm_x4(b00, b01, b10, b11,
                    bbase + slab + (uint32_t)(bRow0 + p * 16) * 128 + kbB);
            #pragma unroll
            for (int mi = 0; mi < 2; mi++) {
                mma16816(c[mi][2*p][0],   c[mi][2*p][1],   c[mi][2*p][2],   c[mi][2*p][3],
                         a[mi][0], a[mi][1], a[mi][2], a[mi][3], b00, b01);
                mma16816(c[mi][2*p+1][0], c[mi][2*p+1][1], c[mi][2*p+1][2], c[mi][2*p+1][3],
                         a[mi][0], a[mi][1], a[mi][2], a[mi][3], b10, b11);
            }
        }
    }

    // ---- epilogue: exp, diag mask, row sums + deferred col-sum butterfly ----
    float rs[2][2];
    rs[0][0] = rs[0][1] = rs[1][0] = rs[1][1] = 0.0f;
    float cs[16];
    #pragma unroll
    for (int v = 0; v < 16; v++) cs[v] = 0.0f;

    #pragma unroll
    for (int ni = 0; ni < 8; ni++) {
        const int lc = wc * 64 + ni * 8 + 2 * q;
        #pragma unroll
        for (int mi = 0; mi < 2; mi++) {
            const int lr0 = wr * 32 + mi * 16 + g;
            const int lr1 = lr0 + 8;
            float v0 = ex2f(c[mi][ni][0] * EXP_SCALE);
            float v1 = ex2f(c[mi][ni][1] * EXP_SCALE);
            float v2 = ex2f(c[mi][ni][2] * EXP_SCALE);
            float v3 = ex2f(c[mi][ni][3] * EXP_SCALE);
            if (diag) {
                if (lr0 == lc)     v0 = 0.0f;
                if (lr0 == lc + 1) v1 = 0.0f;
                if (lr1 == lc)     v2 = 0.0f;
                if (lr1 == lc + 1) v3 = 0.0f;
            }
            rs[mi][0] += v0 + v1;
            rs[mi][1] += v2 + v3;
            cs[2 * ni]     += v0 + v2;
            cs[2 * ni + 1] += v1 + v3;
        }
    }

    if (!diag) {
        #pragma unroll
        for (int i = 0; i < 8; i++) {
            float keep = (lane & 4) ? cs[i + 8] : cs[i];
            float give = (lane & 4) ? cs[i] : cs[i + 8];
            cs[i] = keep + __shfl_xor_sync(0xffffffffu, give, 4);
        }
        #pragma unroll
        for (int i = 0; i < 4; i++) {
            float keep = (lane & 8) ? cs[i + 4] : cs[i];
            float give = (lane & 8) ? cs[i] : cs[i + 4];
            cs[i] = keep + __shfl_xor_sync(0xffffffffu, give, 8);
        }
        #pragma unroll
        for (int i = 0; i < 2; i++) {
            float keep = (lane & 16) ? cs[i + 2] : cs[i];
            float give = (lane & 16) ? cs[i] : cs[i + 2];
            cs[i] = keep + __shfl_xor_sync(0xffffffffu, give, 16);
        }
        const int v0 = ((lane & 4) ? 8 : 0) + ((lane & 8) ? 4 : 0) + ((lane & 16) ? 2 : 0);
        const int col0 = wc * 64 + (v0 >> 1) * 8 + 2 * q;
        scol[wr][col0]     = cs[0];
        scol[wr][col0 + 1] = cs[1];
    }

    #pragma unroll
    for (int mi = 0; mi < 2; mi++) {
        rs[mi][0] += __shfl_xor_sync(0xffffffffu, rs[mi][0], 1);
        rs[mi][0] += __shfl_xor_sync(0xffffffffu, rs[mi][0], 2);
        rs[mi][1] += __shfl_xor_sync(0xffffffffu, rs[mi][1], 1);
        rs[mi][1] += __shfl_xor_sync(0xffffffffu, rs[mi][1], 2);
    }
    if (q == 0) {
        #pragma unroll
        for (int mi = 0; mi < 2; mi++) {
            const int lr = wr * 32 + mi * 16 + g;
            srow[wc][lr]     = rs[mi][0];
            srow[wc][lr + 8] = rs[mi][1];
        }
    }
    __syncthreads();

    if (tid < 128) {
        float v = srow[0][tid] + srow[1][tid];
        g_partial[(rt * 128 + tid) * NTILES + ct] = v;
    } else if (!diag) {
        const int cI = tid - 128;
        float v = scol[0][cI] + scol[1][cI] + scol[2][cI] + scol[3][cI];
        g_partial[(ct * 128 + cI) * NTILES + rt] = v;
    }
}

// ---------------------------------------------------------------------------
// K3: per-row log-sum + per-block positive sums. grid 32 x 256.
__global__ void k_reduce(void) {
    int tid = threadIdx.x;
    int lane = tid & 31, wid = tid >> 5;
    __shared__ float sred1[8], sred2[8];

    int row = blockIdx.x * 256 + tid;
    const float4* p = reinterpret_cast<const float4*>(g_partial + row * NTILES);
    float s = 0.0f;
    #pragma unroll
    for (int i = 0; i < 16; i++) {
        float4 v = p[i];
        s += (v.x + v.y) + (v.z + v.w);
    }
    float lg = logf(s);
    #pragma unroll
    for (int o = 16; o > 0; o >>= 1) lg += __shfl_xor_sync(0xffffffffu, lg, o);
    if (lane == 0) sred1[wid] = lg;

    int pr = blockIdx.x * 128 + (tid >> 1);
    int h  = tid & 1;
    const float4* pa = reinterpret_cast<const float4*>(g_zf + pr * DDIM + h * 64);
    const float4* pb = reinterpret_cast<const float4*>(g_zf + (pr + BROWS) * DDIM + h * 64);
    float d = 0.0f;
    #pragma unroll
    for (int e = 0; e < 16; e++) {
        float4 va = pa[e], vb = pb[e];
        d += va.x * vb.x + va.y * vb.y + va.z * vb.z + va.w * vb.w;
    }
    d += __shfl_xor_sync(0xffffffffu, d, 1);
    float ps = (h == 0) ? d : 0.0f;
    #pragma unroll
    for (int o = 16; o > 0; o >>= 1) ps += __shfl_xor_sync(0xffffffffu, ps, o);
    if (lane == 0) sred2[wid] = ps;

    __syncthreads();
    if (tid == 0) {
        float t1 = 0.0f, t2 = 0.0f;
        #pragma unroll
        for (int i = 0; i < 8; i++) { t1 += sred1[i]; t2 += sred2[i]; }
        g_ploss[blockIdx.x]  = t1;
        g_possum[blockIdx.x] = t2;
    }
}

// ---------------------------------------------------------------------------
// K4: final scalar, single warp: (sum logs - 20 * sum pos) / 8192
__global__ void k_finalize(float* __restrict__ out) {
    int lane = threadIdx.x;
    float acc = g_ploss[lane] - 20.0f * g_possum[lane];
    #pragma unroll
    for (int o = 16; o > 0; o >>= 1) acc += __shfl_xor_sync(0xffffffffu, acc, o);
    if (lane == 0) out[0] = acc / (float)TWOB;
}

// ---------------------------------------------------------------------------
extern "C" void kernel_launch(void* const* d_in, const int* in_sizes, int n_in,
                              void* d_out, int out_size) {
    const float* xi = (const float*)d_in[0];
    const float* xj = (const float*)d_in[1];
    float* out = (float*)d_out;

    k_normalize<<<TWOB / 8, 256>>>(xi, xj);
    k_nop<<<1, 32>>>();
    k_nop<<<1, 32>>>();

    const int smem_bytes = 2 * TILE_BYTES + 1024;   // 66560
    cudaFuncSetAttribute(k_gemm_exp, cudaFuncAttributeMaxDynamicSharedMemorySize, smem_bytes);
    k_gemm_exp<<<NBLOCKS, 256, smem_bytes>>>();

    k_reduce<<<32, 256>>>();
    k_finalize<<<1, 32>>>(out);
}